// round 3
// baseline (speedup 1.0000x reference)
#include <cuda_runtime.h>
#include <math.h>
#include <stddef.h>

// Problem dims
#define TT 512
#define BB 64
#define II 256
#define HH 512
#define OO 256
#define G4 (4*HH)
#define NBLK 128
#define WPAD (HH + 4)      // padded W row stride (floats)

// ---------------- device scratch ----------------
__device__ float g_xp1[(size_t)TT*BB*G4];
__device__ float g_xp2[(size_t)BB*G4];
__device__ float g_hA[(size_t)BB*HH];
__device__ float g_hB[(size_t)BB*HH];
__device__ float g_hs2[(size_t)TT*BB*HH];
__device__ unsigned g_count = 0;
__device__ unsigned g_gen   = 0;

// ---------------- f32x2 helpers ----------------
typedef unsigned long long u64t;

__device__ __forceinline__ void fma2(u64t& acc, u64t a, u64t b) {
    asm volatile("fma.rn.f32x2 %0, %1, %2, %0;" : "+l"(acc) : "l"(a), "l"(b));
}
__device__ __forceinline__ u64t pk2(float x, float y) {
    u64t r; asm("mov.b64 %0, {%1, %2};" : "=l"(r) : "f"(x), "f"(y)); return r;
}
__device__ __forceinline__ float2 unpk2(u64t v) {
    float2 f; asm("mov.b64 {%0, %1}, %2;" : "=f"(f.x), "=f"(f.y) : "l"(v)); return f;
}
__device__ __forceinline__ void cp_async16(void* dst_smem, const void* src_gmem) {
    unsigned d = (unsigned)__cvta_generic_to_shared(dst_smem);
    asm volatile("cp.async.cg.shared.global [%0], [%1], 16;" :: "r"(d), "l"(src_gmem) : "memory");
}

// =================================================================================
// SGEMM with f32x2: C[M,N] = A[M,K] * B[N,K]^T + bias1[N] (+ bias2[N])
// 128x128 tile, BK=8, 256 threads. acc packed over row-pairs (a natural pairs,
// b duplicated into both lanes).
// =================================================================================
__global__ __launch_bounds__(256) void gemm_bias_kernel(
    const float* __restrict__ A, const float* __restrict__ B,
    const float* __restrict__ bias1, const float* __restrict__ bias2,
    float* __restrict__ C, int M, int N, int K)
{
    __shared__ float As[8][128];
    __shared__ float Bs[8][128];

    const int tid  = threadIdx.x;
    const int row0 = blockIdx.y * 128;
    const int col0 = blockIdx.x * 128;

    const int lrow = tid >> 1;
    const int lcol = (tid & 1) << 2;
    const int tr   = (tid >> 4) << 3;
    const int tc   = (tid & 15) << 3;

    u64t acc2[4][8];   // [row-pair][col]
    #pragma unroll
    for (int i = 0; i < 4; i++)
        #pragma unroll
        for (int j = 0; j < 8; j++) acc2[i][j] = 0ull;

    for (int k0 = 0; k0 < K; k0 += 8) {
        float4 av = make_float4(0.f, 0.f, 0.f, 0.f);
        if (row0 + lrow < M)
            av = *(const float4*)(A + (size_t)(row0 + lrow) * K + k0 + lcol);
        As[lcol+0][lrow] = av.x;
        As[lcol+1][lrow] = av.y;
        As[lcol+2][lrow] = av.z;
        As[lcol+3][lrow] = av.w;

        float4 bv = *(const float4*)(B + (size_t)(col0 + lrow) * K + k0 + lcol);
        Bs[lcol+0][lrow] = bv.x;
        Bs[lcol+1][lrow] = bv.y;
        Bs[lcol+2][lrow] = bv.z;
        Bs[lcol+3][lrow] = bv.w;

        __syncthreads();

        #pragma unroll
        for (int kk = 0; kk < 8; kk++) {
            // a row-pairs: natural packing from float4 loads
            ulonglong2 raA = *(const ulonglong2*)&As[kk][tr];       // rows tr..tr+3
            ulonglong2 raB = *(const ulonglong2*)&As[kk][tr + 4];   // rows tr+4..tr+7
            float rb[8];
            *(float4*)(rb)     = *(const float4*)&Bs[kk][tc];
            *(float4*)(rb + 4) = *(const float4*)&Bs[kk][tc + 4];
            u64t rbd[8];
            #pragma unroll
            for (int j = 0; j < 8; j++) rbd[j] = pk2(rb[j], rb[j]);
            #pragma unroll
            for (int j = 0; j < 8; j++) {
                fma2(acc2[0][j], raA.x, rbd[j]);
                fma2(acc2[1][j], raA.y, rbd[j]);
                fma2(acc2[2][j], raB.x, rbd[j]);
                fma2(acc2[3][j], raB.y, rbd[j]);
            }
        }
        __syncthreads();
    }

    float bsum[8];
    #pragma unroll
    for (int j = 0; j < 8; j++) {
        float b = bias1 ? bias1[col0 + tc + j] : 0.f;
        if (bias2) b += bias2[col0 + tc + j];
        bsum[j] = b;
    }

    #pragma unroll
    for (int i2 = 0; i2 < 4; i2++) {
        #pragma unroll
        for (int half = 0; half < 2; half++) {
            int r = row0 + tr + i2 * 2 + half;
            if (r < M) {
                #pragma unroll
                for (int j = 0; j < 8; j += 4) {
                    float4 o;
                    float2 u0 = unpk2(acc2[i2][j+0]);
                    float2 u1 = unpk2(acc2[i2][j+1]);
                    float2 u2 = unpk2(acc2[i2][j+2]);
                    float2 u3 = unpk2(acc2[i2][j+3]);
                    o.x = (half ? u0.y : u0.x) + bsum[j+0];
                    o.y = (half ? u1.y : u1.x) + bsum[j+1];
                    o.z = (half ? u2.y : u2.x) + bsum[j+2];
                    o.w = (half ? u3.y : u3.x) + bsum[j+3];
                    *(float4*)(C + (size_t)r * N + col0 + tc + j) = o;
                }
            }
        }
    }
}

// =================================================================================
// Grid barrier
// =================================================================================
__device__ __forceinline__ unsigned atom_add_acqrel(unsigned* p, unsigned v) {
    unsigned r;
    asm volatile("atom.global.acq_rel.gpu.add.u32 %0, [%1], %2;"
                 : "=r"(r) : "l"(p), "r"(v) : "memory");
    return r;
}
__device__ __forceinline__ unsigned ld_acquire(unsigned* p) {
    unsigned r;
    asm volatile("ld.global.acquire.gpu.u32 %0, [%1];"
                 : "=r"(r) : "l"(p) : "memory");
    return r;
}
__device__ __forceinline__ void grid_barrier(unsigned target) {
    __syncthreads();
    if (threadIdx.x == 0) {
        if (atom_add_acqrel(&g_count, 1u) == NBLK - 1) {
            *(volatile unsigned*)&g_count = 0;
            atom_add_acqrel(&g_gen, 1u);
        } else {
            while (ld_acquire(&g_gen) != target) { __nanosleep(64); }
        }
    }
    __syncthreads();
}

// =================================================================================
// Persistent LSTM layer, f32x2 mainloop.
// 128 blocks x 256 threads. Block owns JT=4 hidden cols (16 gate rows) x 64 batches.
// Thread layout: bg = tid&7 (8 batches each), jj = (tid>>3)&3, ks = tid>>5 (8 k-slices
// of 64 k). Thread tile: 8 batches x 4 gates, f32x2-packed along k.
// h staged via cp.async in 2 chunks, pipelined with compute (warp == ks, so each
// half keeps one warp per SMSP at full rt=2 FMA2 issue).
// =================================================================================
#define JT 4
#define RED4 2048                                     // red float4 count
#define STEP_SMEM_FLOATS (32768 + 16*WPAD + RED4*4)
#define STEP_SMEM_BYTES  (STEP_SMEM_FLOATS * 4)       // 196,864 B

__device__ __forceinline__ float sigf(float x) { return 1.f / (1.f + expf(-x)); }

__global__ __launch_bounds__(256, 1) void lstm_persist_kernel(
    const float* __restrict__ h0, const float* __restrict__ c0,
    float* __restrict__ hA, float* __restrict__ hB,
    const float* __restrict__ W, const float* __restrict__ xp,
    long long xp_t_stride, float* __restrict__ hs_out)
{
    extern __shared__ float smem[];
    float4* hS4  = (float4*)smem;                    // 8192 float4, swizzled h
    float*  wS   = smem + 32768;                     // 16 rows x WPAD
    float4* red4 = (float4*)(smem + 32768 + 16*WPAD);// 2048 float4 partials

    const int tid = threadIdx.x;
    const int bg  = tid & 7;           // 8 batches per group
    const int jj  = (tid >> 3) & 3;
    const int ks  = tid >> 5;          // k-slice 0..7 == warp id
    const int jj0 = blockIdx.x * JT;

    // ---- stage W once ----
    for (int idx = tid; idx < 16 * (HH/4); idx += 256) {
        int r  = idx >> 7;
        int c4 = idx & 127;
        int g  = r >> 2, j = r & 3;
        *(float4*)(wS + r * WPAD + c4 * 4) =
            ((const float4*)(W + (size_t)(g * HH + jj0 + j) * HH))[c4];
    }

    // ---- activation-thread persistent state ----
    const int bq2 = tid & 15, jj2 = tid >> 4;        // valid for tid < 64
    const int jg  = jj0 + jj2;
    float creg[4];
    if (tid < 64) {
        #pragma unroll
        for (int i = 0; i < 4; i++)
            creg[i] = c0[(size_t)(bq2 * 4 + i) * HH + jg];
    }

    unsigned base_gen;
    {
        __shared__ unsigned s_gen;
        if (tid == 0) s_gen = ld_acquire(&g_gen);
        __syncthreads();
        base_gen = s_gen;
    }

    const int b0 = bg << 3;
    const int sw = bg;                               // swizzle key = batch group
    const float* w0 = wS + (0*4 + jj) * WPAD;
    const float* w1 = wS + (1*4 + jj) * WPAD;
    const float* w2 = wS + (2*4 + jj) * WPAD;
    const float* w3 = wS + (3*4 + jj) * WPAD;
    const int k4beg = ks * 16;                       // 16 float4 per k-slice

    for (int t = 0; t < TT; t++) {
        const float* hsrc = (t == 0) ? h0 : ((t & 1) ? hB : hA);
        float*       hdst = (t & 1) ? hA : hB;

        // ---- stage h via cp.async, two k-chunks ----
        #pragma unroll
        for (int half = 0; half < 2; half++) {
            for (int idx = tid; idx < 4096; idx += 256) {
                int b = idx >> 6, k4 = (half << 6) + (idx & 63);
                cp_async16(hS4 + b * 128 + (k4 ^ ((b >> 3) & 7)),
                           (const float4*)hsrc + b * 128 + k4);
            }
            asm volatile("cp.async.commit_group;" ::: "memory");
        }

        // ---- prefetch xp gate inputs ----
        float xi[4], xf[4], xg[4], xo[4];
        if (tid < 64) {
            const float* xt = xp + (size_t)(xp_t_stride * t);
            #pragma unroll
            for (int i = 0; i < 4; i++) {
                const float* xb = xt + (size_t)(bq2 * 4 + i) * G4;
                xi[i] = xb[0*HH + jg];
                xf[i] = xb[1*HH + jg];
                xg[i] = xb[2*HH + jg];
                xo[i] = xb[3*HH + jg];
            }
        }

        u64t acc2[8][4];
        #pragma unroll
        for (int i = 0; i < 8; i++)
            #pragma unroll
            for (int g = 0; g < 4; g++) acc2[i][g] = 0ull;

        // ---- pipelined compute: chunk A (ks<4) under chunk B's loads ----
        asm volatile("cp.async.wait_group 1;" ::: "memory");
        __syncthreads();

        #pragma unroll
        for (int phase = 0; phase < 2; phase++) {
            if ((ks < 4) == (phase == 0)) {
                #pragma unroll 4
                for (int it = 0; it < 16; it++) {
                    int k4 = k4beg + it;
                    ulonglong2 wv0 = *(const ulonglong2*)(w0 + k4 * 4);
                    ulonglong2 wv1 = *(const ulonglong2*)(w1 + k4 * 4);
                    ulonglong2 wv2 = *(const ulonglong2*)(w2 + k4 * 4);
                    ulonglong2 wv3 = *(const ulonglong2*)(w3 + k4 * 4);
                    int kx = k4 ^ sw;
                    #pragma unroll
                    for (int i = 0; i < 8; i++) {
                        ulonglong2 hv = *(const ulonglong2*)(hS4 + ((b0 + i) << 7) + kx);
                        fma2(acc2[i][0], hv.x, wv0.x); fma2(acc2[i][0], hv.y, wv0.y);
                        fma2(acc2[i][1], hv.x, wv1.x); fma2(acc2[i][1], hv.y, wv1.y);
                        fma2(acc2[i][2], hv.x, wv2.x); fma2(acc2[i][2], hv.y, wv2.y);
                        fma2(acc2[i][3], hv.x, wv3.x); fma2(acc2[i][3], hv.y, wv3.y);
                    }
                }
            }
            if (phase == 0) {
                asm volatile("cp.async.wait_group 0;" ::: "memory");
                __syncthreads();
            }
        }

        // ---- write partials (swizzled to avoid bank conflicts) ----
        #pragma unroll
        for (int i = 0; i < 8; i++) {
            float2 a0 = unpk2(acc2[i][0]);
            float2 a1 = unpk2(acc2[i][1]);
            float2 a2 = unpk2(acc2[i][2]);
            float2 a3 = unpk2(acc2[i][3]);
            red4[tid * 8 + (i ^ (tid & 7))] =
                make_float4(a0.x + a0.y, a1.x + a1.y, a2.x + a2.y, a3.x + a3.y);
        }
        __syncthreads();

        // ---- reduce over 8 k-slices + activations + state update ----
        if (tid < 64) {
            #pragma unroll
            for (int i = 0; i < 4; i++) {
                int b  = bq2 * 4 + i;
                int bgg = b >> 3, ii = b & 7;
                float4 s = make_float4(0.f, 0.f, 0.f, 0.f);
                #pragma unroll
                for (int k = 0; k < 8; k++) {
                    int wtid = k * 32 + jj2 * 8 + bgg;
                    float4 p = red4[wtid * 8 + (ii ^ (wtid & 7))];
                    s.x += p.x; s.y += p.y; s.z += p.z; s.w += p.w;
                }
                float gi = sigf (s.x + xi[i]);
                float gf = sigf (s.y + xf[i]);
                float gg = tanhf(s.z + xg[i]);
                float go = sigf (s.w + xo[i]);
                float cn = gf * creg[i] + gi * gg;
                creg[i] = cn;
                float hn = go * tanhf(cn);
                hdst[(size_t)b * HH + jg] = hn;
                if (hs_out)
                    hs_out[(size_t)t * BB * HH + (size_t)b * HH + jg] = hn;
            }
            __threadfence();
        }

        if (t != TT - 1)
            grid_barrier(base_gen + (unsigned)t + 1u);
    }
}

// =================================================================================
// Host launch — 5 graph nodes
// =================================================================================
extern "C" void kernel_launch(void* const* d_in, const int* in_sizes, int n_in,
                              void* d_out, int out_size)
{
    (void)in_sizes; (void)n_in; (void)out_size;
    const float* inputs = (const float*)d_in[0];
    const float* W_ih1  = (const float*)d_in[1];
    const float* W_hh1  = (const float*)d_in[2];
    const float* b_ih1  = (const float*)d_in[3];
    const float* b_hh1  = (const float*)d_in[4];
    const float* W_ih2  = (const float*)d_in[5];
    const float* W_hh2  = (const float*)d_in[6];
    const float* b_ih2  = (const float*)d_in[7];
    const float* b_hh2  = (const float*)d_in[8];
    const float* W_lin  = (const float*)d_in[9];
    const float* b_lin  = (const float*)d_in[10];
    const float* h1_0   = (const float*)d_in[11];
    const float* c1_0   = (const float*)d_in[12];
    const float* h2_0   = (const float*)d_in[13];
    const float* c2_0   = (const float*)d_in[14];
    float* out = (float*)d_out;

    float *xp1, *xp2, *hA, *hB, *hs2;
    cudaGetSymbolAddress((void**)&xp1, g_xp1);
    cudaGetSymbolAddress((void**)&xp2, g_xp2);
    cudaGetSymbolAddress((void**)&hA,  g_hA);
    cudaGetSymbolAddress((void**)&hB,  g_hB);
    cudaGetSymbolAddress((void**)&hs2, g_hs2);

    cudaFuncSetAttribute(lstm_persist_kernel,
                         cudaFuncAttributeMaxDynamicSharedMemorySize,
                         STEP_SMEM_BYTES);

    // xp1 = inputs @ W_ih1^T + b_ih1 + b_hh1
    gemm_bias_kernel<<<dim3(G4/128, (TT*BB)/128), 256>>>(
        inputs, W_ih1, b_ih1, b_hh1, xp1, TT*BB, G4, II);

    // Layer 1 (final h1T lands in hA: t=511 odd -> hA)
    lstm_persist_kernel<<<NBLK, 256, STEP_SMEM_BYTES>>>(
        h1_0, c1_0, hA, hB, W_hh1, xp1, (long long)BB * G4, nullptr);

    // xp2 = h1T @ W_ih2^T + b_ih2 + b_hh2
    gemm_bias_kernel<<<dim3(G4/128, 1), 256>>>(
        hA, W_ih2, b_ih2, b_hh2, xp2, BB, G4, HH);

    // Layer 2
    lstm_persist_kernel<<<NBLK, 256, STEP_SMEM_BYTES>>>(
        h2_0, c2_0, hA, hB, W_hh2, xp2, 0LL, hs2);

    // out = hs2 @ W_lin^T + b_lin
    gemm_bias_kernel<<<dim3(OO/128, (TT*BB)/128), 256>>>(
        hs2, W_lin, b_lin, nullptr, out, TT*BB, OO, HH);
}

// round 4
// speedup vs baseline: 1.0076x; 1.0076x over previous
#include <cuda_runtime.h>
#include <math.h>
#include <stddef.h>

// Problem dims
#define TT 512
#define BB 64
#define II 256
#define HH 512
#define OO 256
#define G4 (4*HH)
#define NBLK 128
#define WPAD (HH + 4)      // padded W row stride (floats)

// ---------------- device scratch ----------------
__device__ float g_xp1[(size_t)TT*BB*G4];
__device__ float g_xp2[(size_t)BB*G4];
__device__ float g_hA[(size_t)BB*HH];
__device__ float g_hB[(size_t)BB*HH];
__device__ float g_hs2[(size_t)TT*BB*HH];
__device__ unsigned g_flags[NBLK];          // zero-init; monotonic per-block step counters

// ---------------- f32x2 / async helpers ----------------
typedef unsigned long long u64t;

__device__ __forceinline__ void fma2(u64t& acc, u64t a, u64t b) {
    asm volatile("fma.rn.f32x2 %0, %1, %2, %0;" : "+l"(acc) : "l"(a), "l"(b));
}
__device__ __forceinline__ u64t pk2(float x, float y) {
    u64t r; asm("mov.b64 %0, {%1, %2};" : "=l"(r) : "f"(x), "f"(y)); return r;
}
__device__ __forceinline__ float2 unpk2(u64t v) {
    float2 f; asm("mov.b64 {%0, %1}, %2;" : "=f"(f.x), "=f"(f.y) : "l"(v)); return f;
}
__device__ __forceinline__ void cp_async16(void* dst_smem, const void* src_gmem) {
    unsigned d = (unsigned)__cvta_generic_to_shared(dst_smem);
    asm volatile("cp.async.cg.shared.global [%0], [%1], 16;" :: "r"(d), "l"(src_gmem) : "memory");
}
__device__ __forceinline__ void st_release(unsigned* p, unsigned v) {
    asm volatile("st.global.release.gpu.u32 [%0], %1;" :: "l"(p), "r"(v) : "memory");
}
__device__ __forceinline__ unsigned ld_acquire(const unsigned* p) {
    unsigned r;
    asm volatile("ld.global.acquire.gpu.u32 %0, [%1];" : "=r"(r) : "l"(p) : "memory");
    return r;
}

// fast activations (rel err ~1e-6; tolerance is 1e-3)
__device__ __forceinline__ float fsig(float x) {
    return __fdividef(1.f, 1.f + __expf(-x));
}
__device__ __forceinline__ float ftanh(float x) {
    return __fdividef(2.f, 1.f + __expf(-2.f * x)) - 1.f;
}

// =================================================================================
// SGEMM with f32x2: C[M,N] = A[M,K] * B[N,K]^T + bias1[N] (+ bias2[N])
// =================================================================================
__global__ __launch_bounds__(256) void gemm_bias_kernel(
    const float* __restrict__ A, const float* __restrict__ B,
    const float* __restrict__ bias1, const float* __restrict__ bias2,
    float* __restrict__ C, int M, int N, int K)
{
    __shared__ float As[8][128];
    __shared__ float Bs[8][128];

    const int tid  = threadIdx.x;
    const int row0 = blockIdx.y * 128;
    const int col0 = blockIdx.x * 128;

    const int lrow = tid >> 1;
    const int lcol = (tid & 1) << 2;
    const int tr   = (tid >> 4) << 3;
    const int tc   = (tid & 15) << 3;

    u64t acc2[4][8];
    #pragma unroll
    for (int i = 0; i < 4; i++)
        #pragma unroll
        for (int j = 0; j < 8; j++) acc2[i][j] = 0ull;

    for (int k0 = 0; k0 < K; k0 += 8) {
        float4 av = make_float4(0.f, 0.f, 0.f, 0.f);
        if (row0 + lrow < M)
            av = *(const float4*)(A + (size_t)(row0 + lrow) * K + k0 + lcol);
        As[lcol+0][lrow] = av.x;
        As[lcol+1][lrow] = av.y;
        As[lcol+2][lrow] = av.z;
        As[lcol+3][lrow] = av.w;

        float4 bv = *(const float4*)(B + (size_t)(col0 + lrow) * K + k0 + lcol);
        Bs[lcol+0][lrow] = bv.x;
        Bs[lcol+1][lrow] = bv.y;
        Bs[lcol+2][lrow] = bv.z;
        Bs[lcol+3][lrow] = bv.w;

        __syncthreads();

        #pragma unroll
        for (int kk = 0; kk < 8; kk++) {
            ulonglong2 raA = *(const ulonglong2*)&As[kk][tr];
            ulonglong2 raB = *(const ulonglong2*)&As[kk][tr + 4];
            float rb[8];
            *(float4*)(rb)     = *(const float4*)&Bs[kk][tc];
            *(float4*)(rb + 4) = *(const float4*)&Bs[kk][tc + 4];
            u64t rbd[8];
            #pragma unroll
            for (int j = 0; j < 8; j++) rbd[j] = pk2(rb[j], rb[j]);
            #pragma unroll
            for (int j = 0; j < 8; j++) {
                fma2(acc2[0][j], raA.x, rbd[j]);
                fma2(acc2[1][j], raA.y, rbd[j]);
                fma2(acc2[2][j], raB.x, rbd[j]);
                fma2(acc2[3][j], raB.y, rbd[j]);
            }
        }
        __syncthreads();
    }

    float bsum[8];
    #pragma unroll
    for (int j = 0; j < 8; j++) {
        float b = bias1 ? bias1[col0 + tc + j] : 0.f;
        if (bias2) b += bias2[col0 + tc + j];
        bsum[j] = b;
    }

    #pragma unroll
    for (int i2 = 0; i2 < 4; i2++) {
        #pragma unroll
        for (int half = 0; half < 2; half++) {
            int r = row0 + tr + i2 * 2 + half;
            if (r < M) {
                #pragma unroll
                for (int j = 0; j < 8; j += 4) {
                    float4 o;
                    float2 u0 = unpk2(acc2[i2][j+0]);
                    float2 u1 = unpk2(acc2[i2][j+1]);
                    float2 u2 = unpk2(acc2[i2][j+2]);
                    float2 u3 = unpk2(acc2[i2][j+3]);
                    o.x = (half ? u0.y : u0.x) + bsum[j+0];
                    o.y = (half ? u1.y : u1.x) + bsum[j+1];
                    o.z = (half ? u2.y : u2.x) + bsum[j+2];
                    o.w = (half ? u3.y : u3.x) + bsum[j+3];
                    *(float4*)(C + (size_t)r * N + col0 + tc + j) = o;
                }
            }
        }
    }
}

// =================================================================================
// Persistent LSTM layer, f32x2 mainloop + flag-array grid barrier.
// 128 blocks x 256 threads. Block owns JT=4 hidden cols (16 gate rows) x 64 batches.
// Compute layout: bg=tid&7 (8 batches), jj=(tid>>3)&3, ks=tid>>5 (8 k-slices).
// Tail layout: 1 cell per thread: cb=tid>>2 (batch), jz=tid&3 (col).
// =================================================================================
#define JT 4
#define RED4 2048
#define STEP_SMEM_FLOATS (32768 + 16*WPAD + RED4*4)
#define STEP_SMEM_BYTES  (STEP_SMEM_FLOATS * 4)       // 196,864 B

__global__ __launch_bounds__(256, 1) void lstm_persist_kernel(
    const float* __restrict__ h0, const float* __restrict__ c0,
    float* __restrict__ hA, float* __restrict__ hB,
    const float* __restrict__ W, const float* __restrict__ xp,
    long long xp_t_stride, float* __restrict__ hs_out)
{
    extern __shared__ float smem[];
    float4* hS4  = (float4*)smem;                     // 8192 float4, swizzled h
    float*  wS   = smem + 32768;                      // 16 rows x WPAD
    float4* red4 = (float4*)(smem + 32768 + 16*WPAD); // 2048 float4 partials

    const int tid = threadIdx.x;
    const int bg  = tid & 7;
    const int jj  = (tid >> 3) & 3;
    const int ks  = tid >> 5;
    const int jj0 = blockIdx.x * JT;

    // ---- stage W once ----
    for (int idx = tid; idx < 16 * (HH/4); idx += 256) {
        int r  = idx >> 7;
        int c4 = idx & 127;
        int g  = r >> 2, j = r & 3;
        *(float4*)(wS + r * WPAD + c4 * 4) =
            ((const float4*)(W + (size_t)(g * HH + jj0 + j) * HH))[c4];
    }

    // ---- per-thread persistent cell state (1 cell per thread) ----
    const int cb = tid >> 2, jz = tid & 3;
    const int jg = jj0 + jz;
    float creg = c0[(size_t)cb * HH + jg];

    // ---- barrier generation base (own slot = count of completed barriers) ----
    unsigned base;
    {
        __shared__ unsigned s_base;
        if (tid == 0) s_base = g_flags[blockIdx.x];
        __syncthreads();
        base = s_base;
    }

    const int b0 = bg << 3;
    const int sw = bg;
    const float* w0 = wS + (0*4 + jj) * WPAD;
    const float* w1 = wS + (1*4 + jj) * WPAD;
    const float* w2 = wS + (2*4 + jj) * WPAD;
    const float* w3 = wS + (3*4 + jj) * WPAD;
    const int k4beg = ks * 16;

    for (int t = 0; t < TT; t++) {
        const float* hsrc = (t == 0) ? h0 : ((t & 1) ? hB : hA);
        float*       hdst = (t & 1) ? hA : hB;

        // ---- prefetch xp gate inputs first (longest latency) ----
        const float* xt = xp + (size_t)(xp_t_stride * t) + (size_t)cb * G4 + jg;
        float xi = xt[0*HH];
        float xf = xt[1*HH];
        float xg = xt[2*HH];
        float xo = xt[3*HH];

        // ---- stage h via cp.async, two k-chunks ----
        #pragma unroll
        for (int half = 0; half < 2; half++) {
            for (int idx = tid; idx < 4096; idx += 256) {
                int b = idx >> 6, k4 = (half << 6) + (idx & 63);
                cp_async16(hS4 + b * 128 + (k4 ^ ((b >> 3) & 7)),
                           (const float4*)hsrc + b * 128 + k4);
            }
            asm volatile("cp.async.commit_group;" ::: "memory");
        }

        u64t acc2[8][4];
        #pragma unroll
        for (int i = 0; i < 8; i++)
            #pragma unroll
            for (int g = 0; g < 4; g++) acc2[i][g] = 0ull;

        asm volatile("cp.async.wait_group 1;" ::: "memory");
        __syncthreads();

        #pragma unroll
        for (int phase = 0; phase < 2; phase++) {
            if ((ks < 4) == (phase == 0)) {
                #pragma unroll 4
                for (int it = 0; it < 16; it++) {
                    int k4 = k4beg + it;
                    ulonglong2 wv0 = *(const ulonglong2*)(w0 + k4 * 4);
                    ulonglong2 wv1 = *(const ulonglong2*)(w1 + k4 * 4);
                    ulonglong2 wv2 = *(const ulonglong2*)(w2 + k4 * 4);
                    ulonglong2 wv3 = *(const ulonglong2*)(w3 + k4 * 4);
                    int kx = k4 ^ sw;
                    #pragma unroll
                    for (int i = 0; i < 8; i++) {
                        ulonglong2 hv = *(const ulonglong2*)(hS4 + ((b0 + i) << 7) + kx);
                        fma2(acc2[i][0], hv.x, wv0.x); fma2(acc2[i][0], hv.y, wv0.y);
                        fma2(acc2[i][1], hv.x, wv1.x); fma2(acc2[i][1], hv.y, wv1.y);
                        fma2(acc2[i][2], hv.x, wv2.x); fma2(acc2[i][2], hv.y, wv2.y);
                        fma2(acc2[i][3], hv.x, wv3.x); fma2(acc2[i][3], hv.y, wv3.y);
                    }
                }
            }
            if (phase == 0) {
                asm volatile("cp.async.wait_group 0;" ::: "memory");
                __syncthreads();
            }
        }

        // ---- write partials (swizzled) ----
        #pragma unroll
        for (int i = 0; i < 8; i++) {
            float2 a0 = unpk2(acc2[i][0]);
            float2 a1 = unpk2(acc2[i][1]);
            float2 a2 = unpk2(acc2[i][2]);
            float2 a3 = unpk2(acc2[i][3]);
            red4[tid * 8 + (i ^ (tid & 7))] =
                make_float4(a0.x + a0.y, a1.x + a1.y, a2.x + a2.y, a3.x + a3.y);
        }
        __syncthreads();

        // ---- tail: every thread owns one (batch, col) cell ----
        {
            float4 s = make_float4(0.f, 0.f, 0.f, 0.f);
            const int cgg = cb >> 3, ii = cb & 7;
            #pragma unroll
            for (int k = 0; k < 8; k++) {
                int p = k * 32 + jz * 8 + cgg;
                float4 q = red4[p * 8 + (ii ^ (p & 7))];
                s.x += q.x; s.y += q.y; s.z += q.z; s.w += q.w;
            }
            float gi = fsig (s.x + xi);
            float gf = fsig (s.y + xf);
            float gg = ftanh(s.z + xg);
            float go = fsig (s.w + xo);
            float cn = gf * creg + gi * gg;
            creg = cn;
            float hn = go * ftanh(cn);
            hdst[(size_t)cb * HH + jg] = hn;
            if (hs_out)
                hs_out[(size_t)t * BB * HH + (size_t)cb * HH + jg] = hn;
        }
        __syncthreads();   // all h stores done (cta-ordered before the release below)

        // ---- flag-array grid barrier ----
        if (t != TT - 1) {
            unsigned target = base + (unsigned)t + 1u;
            if (tid == 0) st_release(&g_flags[blockIdx.x], target);
            if (tid < 32) {
                #pragma unroll
                for (int q = 0; q < 4; q++) {
                    const unsigned* fp = &g_flags[q * 32 + tid];
                    while ((int)(ld_acquire(fp) - target) < 0) { }
                }
            }
            __syncthreads();
        }
    }
}

// =================================================================================
// Host launch — 5 graph nodes
// =================================================================================
extern "C" void kernel_launch(void* const* d_in, const int* in_sizes, int n_in,
                              void* d_out, int out_size)
{
    (void)in_sizes; (void)n_in; (void)out_size;
    const float* inputs = (const float*)d_in[0];
    const float* W_ih1  = (const float*)d_in[1];
    const float* W_hh1  = (const float*)d_in[2];
    const float* b_ih1  = (const float*)d_in[3];
    const float* b_hh1  = (const float*)d_in[4];
    const float* W_ih2  = (const float*)d_in[5];
    const float* W_hh2  = (const float*)d_in[6];
    const float* b_ih2  = (const float*)d_in[7];
    const float* b_hh2  = (const float*)d_in[8];
    const float* W_lin  = (const float*)d_in[9];
    const float* b_lin  = (const float*)d_in[10];
    const float* h1_0   = (const float*)d_in[11];
    const float* c1_0   = (const float*)d_in[12];
    const float* h2_0   = (const float*)d_in[13];
    const float* c2_0   = (const float*)d_in[14];
    float* out = (float*)d_out;

    float *xp1, *xp2, *hA, *hB, *hs2;
    cudaGetSymbolAddress((void**)&xp1, g_xp1);
    cudaGetSymbolAddress((void**)&xp2, g_xp2);
    cudaGetSymbolAddress((void**)&hA,  g_hA);
    cudaGetSymbolAddress((void**)&hB,  g_hB);
    cudaGetSymbolAddress((void**)&hs2, g_hs2);

    cudaFuncSetAttribute(lstm_persist_kernel,
                         cudaFuncAttributeMaxDynamicSharedMemorySize,
                         STEP_SMEM_BYTES);

    // xp1 = inputs @ W_ih1^T + b_ih1 + b_hh1
    gemm_bias_kernel<<<dim3(G4/128, (TT*BB)/128), 256>>>(
        inputs, W_ih1, b_ih1, b_hh1, xp1, TT*BB, G4, II);

    // Layer 1 (final h1T lands in hA: t=511 odd -> hA)
    lstm_persist_kernel<<<NBLK, 256, STEP_SMEM_BYTES>>>(
        h1_0, c1_0, hA, hB, W_hh1, xp1, (long long)BB * G4, nullptr);

    // xp2 = h1T @ W_ih2^T + b_ih2 + b_hh2
    gemm_bias_kernel<<<dim3(G4/128, 1), 256>>>(
        hA, W_ih2, b_ih2, b_hh2, xp2, BB, G4, HH);

    // Layer 2
    lstm_persist_kernel<<<NBLK, 256, STEP_SMEM_BYTES>>>(
        h2_0, c2_0, hA, hB, W_hh2, xp2, 0LL, hs2);

    // out = hs2 @ W_lin^T + b_lin
    gemm_bias_kernel<<<dim3(OO/128, (TT*BB)/128), 256>>>(
        hs2, W_lin, b_lin, nullptr, out, TT*BB, OO, HH);
}